// round 7
// baseline (speedup 1.0000x reference)
#include <cuda_runtime.h>
#include <cuda_bf16.h>
#include <cstdint>

// Problem constants
#define T_LEN   1024
#define BSZ     4
#define EMBED   1024
#define NHEADS  16
#define HDIM    64
#define NBH     (BSZ * NHEADS)      // 64
#define MROWS   (T_LEN * BSZ)       // 4096
#define SCALING 0.125f

// bf16 hi/lo scratch (q scaled)
__device__ __nv_bfloat16 g_qh[NBH * T_LEN * HDIM];
__device__ __nv_bfloat16 g_ql[NBH * T_LEN * HDIM];
__device__ __nv_bfloat16 g_kh[NBH * T_LEN * HDIM];
__device__ __nv_bfloat16 g_kl[NBH * T_LEN * HDIM];
__device__ __nv_bfloat16 g_vh[NBH * T_LEN * HDIM];
__device__ __nv_bfloat16 g_vl[NBH * T_LEN * HDIM];
__device__ __nv_bfloat16 g_attnh[MROWS * EMBED];
__device__ __nv_bfloat16 g_attnl[MROWS * EMBED];
// bf16 split GEMM operands
__device__ __nv_bfloat16 g_Ah[MROWS * EMBED];
__device__ __nv_bfloat16 g_Al[MROWS * EMBED];
__device__ __nv_bfloat16 g_Bh[3 * EMBED * EMBED];
__device__ __nv_bfloat16 g_Bl[3 * EMBED * EMBED];

// ---------------------------------------------------------------------------
// PTX helpers
// ---------------------------------------------------------------------------
__device__ __forceinline__ uint32_t s2u(const void* p) {
    return (uint32_t)__cvta_generic_to_shared(p);
}
__device__ __forceinline__ void cp_async16(uint32_t dst, const void* src) {
    asm volatile("cp.async.cg.shared.global [%0], [%1], 16;\n" :: "r"(dst), "l"(src));
}
__device__ __forceinline__ void cp_commit() {
    asm volatile("cp.async.commit_group;\n");
}
template<int N>
__device__ __forceinline__ void cp_wait() {
    asm volatile("cp.async.wait_group %0;\n" :: "n"(N));
}
__device__ __forceinline__ void ldm_x4(uint32_t* r, uint32_t addr) {
    asm volatile("ldmatrix.sync.aligned.m8n8.x4.shared.b16 {%0,%1,%2,%3}, [%4];"
                 : "=r"(r[0]), "=r"(r[1]), "=r"(r[2]), "=r"(r[3]) : "r"(addr));
}
__device__ __forceinline__ void ldm_x4_trans(uint32_t* r, uint32_t addr) {
    asm volatile("ldmatrix.sync.aligned.m8n8.x4.trans.shared.b16 {%0,%1,%2,%3}, [%4];"
                 : "=r"(r[0]), "=r"(r[1]), "=r"(r[2]), "=r"(r[3]) : "r"(addr));
}
__device__ __forceinline__ void mma16816(float* c, const uint32_t* a, const uint32_t* b) {
    asm volatile("mma.sync.aligned.m16n8k16.row.col.f32.bf16.bf16.f32 "
                 "{%0,%1,%2,%3}, {%4,%5,%6,%7}, {%8,%9}, {%0,%1,%2,%3};"
                 : "+f"(c[0]), "+f"(c[1]), "+f"(c[2]), "+f"(c[3])
                 : "r"(a[0]), "r"(a[1]), "r"(a[2]), "r"(a[3]), "r"(b[0]), "r"(b[1]));
}
__device__ __host__ __forceinline__ uint32_t sw128(uint32_t off) {
    return off ^ ((off >> 3) & 0x70);
}
__device__ __forceinline__ uint32_t pack_hi2(float a, float b) {
    __nv_bfloat162 t; t.x = __float2bfloat16(a); t.y = __float2bfloat16(b);
    uint32_t r; memcpy(&r, &t, 4); return r;
}
__device__ __forceinline__ uint32_t pack_lo2(float a, float b) {
    __nv_bfloat16 ha = __float2bfloat16(a), hb = __float2bfloat16(b);
    __nv_bfloat162 t;
    t.x = __float2bfloat16(a - __bfloat162float(ha));
    t.y = __float2bfloat16(b - __bfloat162float(hb));
    uint32_t r; memcpy(&r, &t, 4); return r;
}

// ---------------------------------------------------------------------------
// fp32 -> (hi, lo) bf16 split
// ---------------------------------------------------------------------------
__global__ __launch_bounds__(256)
void split_kernel(const float* __restrict__ src, __nv_bfloat16* __restrict__ hi,
                  __nv_bfloat16* __restrict__ lo, int n4)
{
    int i = blockIdx.x * 256 + threadIdx.x;
    if (i >= n4) return;
    float4 v = reinterpret_cast<const float4*>(src)[i];
    reinterpret_cast<uint32_t*>(hi)[2 * i]     = pack_hi2(v.x, v.y);
    reinterpret_cast<uint32_t*>(hi)[2 * i + 1] = pack_hi2(v.z, v.w);
    reinterpret_cast<uint32_t*>(lo)[2 * i]     = pack_lo2(v.x, v.y);
    reinterpret_cast<uint32_t*>(lo)[2 * i + 1] = pack_lo2(v.z, v.w);
}

// ---------------------------------------------------------------------------
// mma.sync split-bf16 GEMM — 3-stage pipeline, x4 B-frag loads
// ---------------------------------------------------------------------------
#define GK 1024
#define TM 128
#define TN 128
#define TBK 32
#define NKS (GK / TBK)
#define A_ST 40
#define TILE_B (128 * A_ST * 2)
#define STAGE_B (4 * TILE_B)
#define GEMM_SMEM (3 * STAGE_B)   // 122880

__device__ __forceinline__ void load_stage(uint32_t sbase,
    const __nv_bfloat16* __restrict__ Ah, const __nv_bfloat16* __restrict__ Al,
    const __nv_bfloat16* __restrict__ Bh, const __nv_bfloat16* __restrict__ Bl,
    int row0, int col0, int k0, int tid)
{
#pragma unroll
    for (int it = 0; it < 2; it++) {
        int idx = it * 256 + tid;
        int r = idx >> 2, c = idx & 3;
        uint32_t so = r * (A_ST * 2) + c * 16;
        size_t ga = (size_t)(row0 + r) * GK + k0 + c * 8;
        size_t gb = (size_t)(col0 + r) * GK + k0 + c * 8;
        cp_async16(sbase + 0 * TILE_B + so, Ah + ga);
        cp_async16(sbase + 1 * TILE_B + so, Al + ga);
        cp_async16(sbase + 2 * TILE_B + so, Bh + gb);
        cp_async16(sbase + 3 * TILE_B + so, Bl + gb);
    }
}

__global__ __launch_bounds__(256)
void gemm_mma(const __nv_bfloat16* __restrict__ Ah, const __nv_bfloat16* __restrict__ Al,
              const __nv_bfloat16* __restrict__ Bh, const __nv_bfloat16* __restrict__ Bl,
              const float* __restrict__ bias, int mode, float* __restrict__ out)
{
    extern __shared__ char smc[];
    const uint32_t sb = s2u(smc);
    const int tid  = threadIdx.x;
    const int lane = tid & 31;
    const int wid  = tid >> 5;
    const int wr = wid & 1;
    const int wc = wid >> 1;
    const int row0 = blockIdx.y * TM, col0 = blockIdx.x * TN;

    const int a_row = lane & 15;
    const int a_k8  = (lane >> 4) * 8;
    // x4 B-frag addressing: matrix = lane>>3
    const int b_mat = lane >> 3;
    const int b_nf_off = b_mat >> 1;          // 0 or 1 (which nf of the pair)
    const int b_k8  = (b_mat & 1) * 8;
    const int b_row = lane & 7;

    float acc[4][4][4];
#pragma unroll
    for (int i = 0; i < 4; i++)
#pragma unroll
        for (int j = 0; j < 4; j++)
#pragma unroll
            for (int q = 0; q < 4; q++) acc[i][j][q] = 0.f;

    load_stage(sb, Ah, Al, Bh, Bl, row0, col0, 0, tid);
    cp_commit();
    load_stage(sb + STAGE_B, Ah, Al, Bh, Bl, row0, col0, TBK, tid);
    cp_commit();

    int cur = 0;
    for (int ks = 0; ks < NKS; ks++) {
        if (ks + 2 < NKS) cp_wait<1>(); else cp_wait<0>();
        __syncthreads();
        if (ks + 2 < NKS) {
            int nxt = cur + 2; if (nxt >= 3) nxt -= 3;
            load_stage(sb + (uint32_t)nxt * STAGE_B,
                       Ah, Al, Bh, Bl, row0, col0, (ks + 2) * TBK, tid);
            cp_commit();
        }
        const uint32_t curb = sb + (uint32_t)cur * STAGE_B;

#pragma unroll
        for (int kk = 0; kk < 2; kk++) {
            const int k0 = kk * 16;
            uint32_t afh[4][4], afl[4][4];
#pragma unroll
            for (int mf = 0; mf < 4; mf++) {
                uint32_t aoff = (uint32_t)((wr * 64 + mf * 16 + a_row) * A_ST + k0 + a_k8) * 2;
                ldm_x4(afh[mf], curb + 0 * TILE_B + aoff);
                ldm_x4(afl[mf], curb + 1 * TILE_B + aoff);
            }
            uint32_t bfh[2][4], bfl[2][4];
#pragma unroll
            for (int nfp = 0; nfp < 2; nfp++) {
                uint32_t boff = (uint32_t)((wc * 32 + (2 * nfp + b_nf_off) * 8 + b_row) * A_ST
                                           + k0 + b_k8) * 2;
                ldm_x4(bfh[nfp], curb + 2 * TILE_B + boff);
                ldm_x4(bfl[nfp], curb + 3 * TILE_B + boff);
            }
#pragma unroll
            for (int mf = 0; mf < 4; mf++)
#pragma unroll
                for (int nfp = 0; nfp < 2; nfp++)
#pragma unroll
                    for (int half = 0; half < 2; half++) {
                        const int nf = 2 * nfp + half;
                        mma16816(acc[mf][nf], afh[mf], bfh[nfp] + half * 2);
                        mma16816(acc[mf][nf], afh[mf], bfl[nfp] + half * 2);
                        mma16816(acc[mf][nf], afl[mf], bfh[nfp] + half * 2);
                    }
        }
        cur++; if (cur >= 3) cur -= 3;
    }

    const int g = lane >> 2, tig = lane & 3;
#pragma unroll
    for (int nf = 0; nf < 4; nf++) {
        const int e = col0 + wc * 32 + nf * 8 + tig * 2;
        const float bz0 = __ldg(bias + e);
        const float bz1 = __ldg(bias + e + 1);
#pragma unroll
        for (int mf = 0; mf < 4; mf++) {
#pragma unroll
            for (int half = 0; half < 2; half++) {
                const int m = row0 + wr * 64 + mf * 16 + g + half * 8;
                float v0 = acc[mf][nf][half * 2 + 0] + bz0;
                float v1 = acc[mf][nf][half * 2 + 1] + bz1;
                if (mode == 0) {
                    const int t = m >> 2, b = m & 3;
                    const int which = e >> 10;
                    const int rem = e & 1023;
                    const int h = rem >> 6, d = rem & 63;
                    const int n = (b << 4) + h;
                    if (which == 0) { v0 *= SCALING; v1 *= SCALING; }
                    __nv_bfloat16* dh = (which == 0) ? g_qh : (which == 1) ? g_kh : g_vh;
                    __nv_bfloat16* dl = (which == 0) ? g_ql : (which == 1) ? g_kl : g_vl;
                    size_t off = ((size_t)n << 16) + ((size_t)t << 6) + d;
                    *reinterpret_cast<uint32_t*>(dh + off) = pack_hi2(v0, v1);
                    *reinterpret_cast<uint32_t*>(dl + off) = pack_lo2(v0, v1);
                } else {
                    *reinterpret_cast<float2*>(out + (size_t)m * EMBED + e)
                        = make_float2(v0, v1);
                }
            }
        }
    }
}

// ---------------------------------------------------------------------------
// Flash attention — software-pipelined: S(b) ; PV(b-1) ; softmax(b).
// Q fragments loaded from global (no Q smem). 3 smem stages.
// ---------------------------------------------------------------------------
#define ABT 128
#define ABS 64
#define NBLK (T_LEN / ABS)   // 16
// per stage: Kh 8K | Kl 8K | Vh 8K | Vl 8K | bias 128xBIAS_ST f | kpm 256B
#define S_KH    0
#define S_KL    8192
#define S_VH    16384
#define S_VL    24576
#define S_BIAS  32768
#define BIAS_ST 68
#define S_KPM   (32768 + 128 * BIAS_ST * 4)   // 67584
#define AST_STRIDE (S_KPM + 256)              // 67840
#define ATTN_SMEM (3 * AST_STRIDE)            // 203520

__device__ __forceinline__ void attn_load_stage(
    uint32_t B, int s0, int t0, const int* __restrict__ kpmg,
    const float* __restrict__ biasg, size_t nbase, int tid)
{
#pragma unroll
    for (int it = 0; it < 2; it++) {
        int idx = it * 256 + tid;
        int row = idx >> 3, c = idx & 7;
        uint32_t so = sw128(row * 128 + c * 16);
        size_t go = nbase + (size_t)(s0 + row) * 64 + c * 8;
        cp_async16(B + S_KH + so, g_kh + go);
        cp_async16(B + S_KL + so, g_kl + go);
        cp_async16(B + S_VH + so, g_vh + go);
        cp_async16(B + S_VL + so, g_vl + go);
    }
#pragma unroll
    for (int it = 0; it < 8; it++) {
        int idx = it * 256 + tid;
        int row = idx >> 4, c = idx & 15;
        cp_async16(B + S_BIAS + row * (BIAS_ST * 4) + c * 16,
                   biasg + (size_t)(t0 + row) * T_LEN + s0 + c * 4);
    }
    if (tid < 16) cp_async16(B + S_KPM + tid * 16, kpmg + s0 + tid * 4);
}

__global__ __launch_bounds__(256, 1)
void attn_mma_kernel(const int*   __restrict__ kpm,
                     const float* __restrict__ attn_mask,
                     const float* __restrict__ attn_bias)
{
    extern __shared__ char smc[];
    const uint32_t sb = s2u(smc);
    const int tid = threadIdx.x, lane = tid & 31, wid = tid >> 5;
    const int n = blockIdx.y, t0 = blockIdx.x * ABT;
    const int b = n >> 4, h = n & 15;
    const int wr0 = wid * 16;
    const int g = lane >> 2, qr = lane & 3;
    const int* kpmg = kpm + b * T_LEN;
    const size_t nbase = (size_t)n << 16;
    const float* biasg = attn_bias + (size_t)n * T_LEN * T_LEN;

    const int tr0 = t0 + wr0 + g, tr1 = tr0 + 8;
    const int tl0 = wr0 + g;

    // ---- Q fragments straight from global ----
    uint32_t qfh[4][4], qfl[4][4];
    {
        const uint32_t* QH = reinterpret_cast<const uint32_t*>(g_qh + nbase);
        const uint32_t* QL = reinterpret_cast<const uint32_t*>(g_ql + nbase);
        // uint32 index: (row*64 + col)/2 = row*32 + col/2
#pragma unroll
        for (int ks = 0; ks < 4; ks++) {
            const int c2 = (ks * 16 + qr * 2) >> 1;   // col/2
            qfh[ks][0] = __ldg(QH + (size_t)tr0 * 32 + c2);
            qfh[ks][1] = __ldg(QH + (size_t)tr1 * 32 + c2);
            qfh[ks][2] = __ldg(QH + (size_t)tr0 * 32 + c2 + 4);
            qfh[ks][3] = __ldg(QH + (size_t)tr1 * 32 + c2 + 4);
            qfl[ks][0] = __ldg(QL + (size_t)tr0 * 32 + c2);
            qfl[ks][1] = __ldg(QL + (size_t)tr1 * 32 + c2);
            qfl[ks][2] = __ldg(QL + (size_t)tr0 * 32 + c2 + 4);
            qfl[ks][3] = __ldg(QL + (size_t)tr1 * 32 + c2 + 4);
        }
    }

    attn_load_stage(sb, 0, t0, kpmg, biasg, nbase, tid);
    cp_commit();

    float m0 = -1e30f, m1 = -1e30f, l0 = 0.f, l1 = 0.f;
    float O[8][4];
#pragma unroll
    for (int i = 0; i < 8; i++)
#pragma unroll
        for (int q = 0; q < 4; q++) O[i][q] = 0.f;
    uint32_t pah[4][4], pal[4][4];    // packed P of previous block

    // x4 K addressing
    const int k_mat = lane >> 3;
    const int k_nf_off = k_mat >> 1;
    const int k_k8 = (k_mat & 1) * 8;
    const int k_row = lane & 7;
    // x4 V addressing (trans)
    const int v_blk = lane >> 4;          // which nf2 of the pair
    const int v_row = lane & 15;

    int cur = 0;
    for (int blk = 0; blk < NBLK; blk++) {
        cp_wait<0>();
        __syncthreads();
        int nxt = cur + 1; if (nxt >= 3) nxt -= 3;
        int prv = cur - 1; if (prv < 0) prv += 3;
        if (blk + 1 < NBLK) {
            attn_load_stage(sb + (uint32_t)nxt * AST_STRIDE, (blk + 1) * ABS,
                            t0, kpmg, biasg, nbase, tid);
            cp_commit();
        }

        // mask prefetch (consumed in softmax phase)
        float2 mk0[8], mk1[8];
        {
            const int s0g = blk * ABS;
#pragma unroll
            for (int nf = 0; nf < 8; nf++) {
                const int scol = s0g + nf * 8 + qr * 2;
                mk0[nf] = __ldg(reinterpret_cast<const float2*>(attn_mask + (size_t)tr0 * T_LEN + scol));
                mk1[nf] = __ldg(reinterpret_cast<const float2*>(attn_mask + (size_t)tr1 * T_LEN + scol));
            }
        }

        const uint32_t B = sb + (uint32_t)cur * AST_STRIDE;

        // ---- Phase A: S = Q K^T ----
        float S[8][4];
#pragma unroll
        for (int i = 0; i < 8; i++)
#pragma unroll
            for (int q = 0; q < 4; q++) S[i][q] = 0.f;
#pragma unroll
        for (int ks = 0; ks < 4; ks++) {
#pragma unroll
            for (int nfp = 0; nfp < 4; nfp++) {
                uint32_t boff = sw128((uint32_t)((2 * nfp + k_nf_off) * 8 + k_row) * 128 +
                                      (uint32_t)(ks * 16 + k_k8) * 2);
                uint32_t kh[4], kl[4];
                ldm_x4(kh, B + S_KH + boff);
                ldm_x4(kl, B + S_KL + boff);
#pragma unroll
                for (int half = 0; half < 2; half++) {
                    const int nf = 2 * nfp + half;
                    mma16816(S[nf], qfh[ks], kh + half * 2);
                    mma16816(S[nf], qfh[ks], kl + half * 2);
                    mma16816(S[nf], qfl[ks], kh + half * 2);
                }
            }
        }

        // ---- Phase B: O += P(b-1) V(b-1) ----
        if (blk > 0) {
            const uint32_t VB = sb + (uint32_t)prv * AST_STRIDE;
#pragma unroll
            for (int kp = 0; kp < 4; kp++) {
#pragma unroll
                for (int np = 0; np < 4; np++) {
                    uint32_t voff = sw128((uint32_t)(kp * 16 + v_row) * 128 +
                                          (uint32_t)(2 * np + v_blk) * 16);
                    uint32_t vh[4], vl[4];
                    ldm_x4_trans(vh, VB + S_VH + voff);
                    ldm_x4_trans(vl, VB + S_VL + voff);
#pragma unroll
                    for (int half = 0; half < 2; half++) {
                        const int nf2 = 2 * np + half;
                        mma16816(O[nf2], pah[kp], vh + half * 2);
                        mma16816(O[nf2], pah[kp], vl + half * 2);
                        mma16816(O[nf2], pal[kp], vh + half * 2);
                    }
                }
            }
        }

        // ---- Phase C: softmax(b) ----
        const int*   kpms   = (const int*)(smc + (size_t)cur * AST_STRIDE + S_KPM);
        const float* bias_s = (const float*)(smc + (size_t)cur * AST_STRIDE + S_BIAS);
        float rmax0 = -1e30f, rmax1 = -1e30f;
#pragma unroll
        for (int nf = 0; nf < 8; nf++) {
            const int sloc = nf * 8 + qr * 2;
            const int k0 = kpms[sloc], k1 = kpms[sloc + 1];
            float2 ba = *reinterpret_cast<const float2*>(bias_s + (size_t)tl0 * BIAS_ST + sloc);
            float2 bb = *reinterpret_cast<const float2*>(bias_s + (size_t)(tl0 + 8) * BIAS_ST + sloc);
            S[nf][0] = k0 ? -1e30f : S[nf][0] + mk0[nf].x + ba.x;
            S[nf][1] = k1 ? -1e30f : S[nf][1] + mk0[nf].y + ba.y;
            S[nf][2] = k0 ? -1e30f : S[nf][2] + mk1[nf].x + bb.x;
            S[nf][3] = k1 ? -1e30f : S[nf][3] + mk1[nf].y + bb.y;
            rmax0 = fmaxf(rmax0, fmaxf(S[nf][0], S[nf][1]));
            rmax1 = fmaxf(rmax1, fmaxf(S[nf][2], S[nf][3]));
        }
        rmax0 = fmaxf(rmax0, __shfl_xor_sync(0xffffffffu, rmax0, 1));
        rmax0 = fmaxf(rmax0, __shfl_xor_sync(0xffffffffu, rmax0, 2));
        rmax1 = fmaxf(rmax1, __shfl_xor_sync(0xffffffffu, rmax1, 1));
        rmax1 = fmaxf(rmax1, __shfl_xor_sync(0xffffffffu, rmax1, 2));

        const float mn0 = fmaxf(m0, rmax0), mn1 = fmaxf(m1, rmax1);
        const float es0 = __expf(m0 - mn0), es1 = __expf(m1 - mn1);
        m0 = mn0; m1 = mn1;

        float rs0 = 0.f, rs1 = 0.f;
#pragma unroll
        for (int nf = 0; nf < 8; nf++) {
            S[nf][0] = __expf(S[nf][0] - mn0);
            S[nf][1] = __expf(S[nf][1] - mn0);
            S[nf][2] = __expf(S[nf][2] - mn1);
            S[nf][3] = __expf(S[nf][3] - mn1);
            rs0 += S[nf][0] + S[nf][1];
            rs1 += S[nf][2] + S[nf][3];
        }
        rs0 += __shfl_xor_sync(0xffffffffu, rs0, 1);
        rs0 += __shfl_xor_sync(0xffffffffu, rs0, 2);
        rs1 += __shfl_xor_sync(0xffffffffu, rs1, 1);
        rs1 += __shfl_xor_sync(0xffffffffu, rs1, 2);
        l0 = l0 * es0 + rs0;
        l1 = l1 * es1 + rs1;

        // rescale O (includes PV(b-1) just added)
#pragma unroll
        for (int i = 0; i < 8; i++) {
            O[i][0] *= es0; O[i][1] *= es0;
            O[i][2] *= es1; O[i][3] *= es1;
        }

        // pack P(b) for next iteration's PV
#pragma unroll
        for (int kp = 0; kp < 4; kp++) {
            pah[kp][0] = pack_hi2(S[2*kp][0],   S[2*kp][1]);
            pah[kp][1] = pack_hi2(S[2*kp][2],   S[2*kp][3]);
            pah[kp][2] = pack_hi2(S[2*kp+1][0], S[2*kp+1][1]);
            pah[kp][3] = pack_hi2(S[2*kp+1][2], S[2*kp+1][3]);
            pal[kp][0] = pack_lo2(S[2*kp][0],   S[2*kp][1]);
            pal[kp][1] = pack_lo2(S[2*kp][2],   S[2*kp][3]);
            pal[kp][2] = pack_lo2(S[2*kp+1][0], S[2*kp+1][1]);
            pal[kp][3] = pack_lo2(S[2*kp+1][2], S[2*kp+1][3]);
        }

        cur = nxt;
    }

    // ---- final PV(NBLK-1); buffer index (NBLK-1)%3 ----
    {
        const uint32_t VB = sb + (uint32_t)((NBLK - 1) % 3) * AST_STRIDE;
#pragma unroll
        for (int kp = 0; kp < 4; kp++) {
#pragma unroll
            for (int np = 0; np < 4; np++) {
                uint32_t voff = sw128((uint32_t)(kp * 16 + v_row) * 128 +
                                      (uint32_t)(2 * np + v_blk) * 16);
                uint32_t vh[4], vl[4];
                ldm_x4_trans(vh, VB + S_VH + voff);
                ldm_x4_trans(vl, VB + S_VL + voff);
#pragma unroll
                for (int half = 0; half < 2; half++) {
                    const int nf2 = 2 * np + half;
                    mma16816(O[nf2], pah[kp], vh + half * 2);
                    mma16816(O[nf2], pah[kp], vl + half * 2);
                    mma16816(O[nf2], pal[kp], vh + half * 2);
                }
            }
        }
    }

    // ---- normalize + write bf16 hi/lo ----
    const float inv0 = 1.f / l0, inv1 = 1.f / l1;
    const size_t base0 = ((size_t)tr0 * BSZ + b) * EMBED + h * 64;
    const size_t base1 = ((size_t)tr1 * BSZ + b) * EMBED + h * 64;
#pragma unroll
    for (int nf2 = 0; nf2 < 8; nf2++) {
        const int d0 = nf2 * 8 + qr * 2;
        float v0 = O[nf2][0] * inv0, v1 = O[nf2][1] * inv0;
        float w0 = O[nf2][2] * inv1, w1 = O[nf2][3] * inv1;
        *reinterpret_cast<uint32_t*>(g_attnh + base0 + d0) = pack_hi2(v0, v1);
        *reinterpret_cast<uint32_t*>(g_attnl + base0 + d0) = pack_lo2(v0, v1);
        *reinterpret_cast<uint32_t*>(g_attnh + base1 + d0) = pack_hi2(w0, w1);
        *reinterpret_cast<uint32_t*>(g_attnl + base1 + d0) = pack_lo2(w0, w1);
    }
}

// ---------------------------------------------------------------------------
extern "C" void kernel_launch(void* const* d_in, const int* in_sizes, int n_in,
                              void* d_out, int out_size)
{
    const float* query     = (const float*)d_in[0];
    const int*   kpm       = (const int*)  d_in[1];
    const float* attn_mask = (const float*)d_in[2];
    const float* attn_bias = (const float*)d_in[3];
    const float* W_in      = (const float*)d_in[4];
    const float* b_in      = (const float*)d_in[5];
    const float* W_out     = (const float*)d_in[6];
    const float* b_out     = (const float*)d_in[7];
    float*       out       = (float*)d_out;

    static bool attr_set = false;
    if (!attr_set) {
        cudaFuncSetAttribute(gemm_mma, cudaFuncAttributeMaxDynamicSharedMemorySize, GEMM_SMEM);
        cudaFuncSetAttribute(attn_mma_kernel, cudaFuncAttributeMaxDynamicSharedMemorySize, ATTN_SMEM);
        attr_set = true;
    }

    __nv_bfloat16 *Ah, *Al, *Bh, *Bl, *ATh, *ATl;
    cudaGetSymbolAddress((void**)&Ah, g_Ah);
    cudaGetSymbolAddress((void**)&Al, g_Al);
    cudaGetSymbolAddress((void**)&Bh, g_Bh);
    cudaGetSymbolAddress((void**)&Bl, g_Bl);
    cudaGetSymbolAddress((void**)&ATh, g_attnh);
    cudaGetSymbolAddress((void**)&ATl, g_attnl);

    // 1) split query and W_in to bf16 pairs
    split_kernel<<<MROWS * EMBED / 4 / 256, 256>>>(query, Ah, Al, MROWS * EMBED / 4);
    split_kernel<<<3 * EMBED * EMBED / 4 / 256, 256>>>(W_in, Bh, Bl, 3 * EMBED * EMBED / 4);

    // 2) QKV projection -> bf16 hi/lo q,k,v
    {
        dim3 grid(3 * EMBED / TN, MROWS / TM);
        gemm_mma<<<grid, 256, GEMM_SMEM>>>(Ah, Al, Bh, Bl, b_in, 0, nullptr);
    }

    // 3) Flash attention (software-pipelined)
    {
        dim3 grid(T_LEN / ABT, NBH);   // (8, 64)
        attn_mma_kernel<<<grid, 256, ATTN_SMEM>>>(kpm, attn_mask, attn_bias);
    }

    // 4) split W_out; output projection (A = attn bf16 pairs)
    split_kernel<<<EMBED * EMBED / 4 / 256, 256>>>(W_out, Bh, Bl, EMBED * EMBED / 4);
    {
        dim3 grid(EMBED / TN, MROWS / TM);
        gemm_mma<<<grid, 256, GEMM_SMEM>>>(ATh, ATl, Bh, Bl, b_out, 1, out);
    }
}